// round 14
// baseline (speedup 1.0000x reference)
#include <cuda_runtime.h>
#include <cuda_bf16.h>
#include <cstdint>

#define NROWS  50000
#define KNB    32
#define CDIM   128
#define TOPK   16
#define TROWS  32                         // rows per GEMM tile
#define NTILES ((NROWS + TROWS - 1) / TROWS)   // 1563
#define NMAIN  (NROWS / 8)                // 6250 main blocks (8 rows each)
#define NBLK   (NTILES + NMAIN)           // 7813 total

// ---------------- scratch (device globals; no allocation) ----------------
__device__ __align__(16) float g_M [CDIM * CDIM];     // Wq^T @ Wk
__device__ __align__(16) float g_Ws[CDIM * CDIM];     // triu(W) + triu(W)^T
__device__ __align__(16) float g_qM[(size_t)NROWS * CDIM];  // feat @ M
__device__ __align__(16) float g_fW[(size_t)NROWS * CDIM];  // feat @ Ws
__device__ __align__(16) float g_scores[(size_t)NROWS * KNB];
__device__ int g_tile_done[NTILES];
__device__ int g_colmask[KNB];
__device__ int g_needfix;
__device__ int g_mask_narrow;   // 1 -> mask elements are 1 byte; 0 -> 4 bytes

// coherent L2 load (bypasses the non-coherent RO path) — REQUIRED for data
// written by other blocks within the same kernel launch.
__device__ __forceinline__ float4 ldcg4(const float4* p) {
    float4 v;
    asm volatile("ld.global.cg.v4.f32 {%0,%1,%2,%3}, [%4];"
                 : "=f"(v.x), "=f"(v.y), "=f"(v.z), "=f"(v.w) : "l"(p));
    return v;
}

// ---------------- K0: prep M, Ws, reset flags ----------------
__global__ void prep_kernel(const float* __restrict__ Wq,
                            const float* __restrict__ Wk,
                            const float* __restrict__ W) {
    int c = blockIdx.x;    // 0..127
    int e = threadIdx.x;   // 0..127
    float acc = 0.f;
#pragma unroll 8
    for (int d = 0; d < CDIM; d++)
        acc += Wq[d * CDIM + c] * Wk[d * CDIM + e];
    g_M[c * CDIM + e] = acc;

    float w = (c <= e) ? W[c * CDIM + e] : W[e * CDIM + c];
    g_Ws[c * CDIM + e] = (c == e) ? 2.f * w : w;

    if (c == 0 && e < KNB) g_colmask[e] = 0;
    if (c == 0 && e == KNB) g_needfix = 0;
    if (c == 0 && e == KNB + 1) g_mask_narrow = 0;
    if (c >= 8 && c < 21) {                       // zero 13*128 >= 1563 flags
        int idx = (c - 8) * 128 + e;
        if (idx < NTILES) g_tile_done[idx] = 0;
    }
}

// ---------------- K0b: sniff knn_mask element width ----------------
__global__ void sniff_kernel(const unsigned int* __restrict__ w) {
    const int nwords = NROWS * KNB / 4;
    int bad = 0;
    for (int i = blockIdx.x * blockDim.x + threadIdx.x; i < nwords;
         i += gridDim.x * blockDim.x) {
        unsigned int v = w[i];
        if (v != 0u && v != 1u && v != 0x3F800000u) bad = 1;
    }
    if (bad) g_mask_narrow = 1;
}

// ---------------- K1: unified projection + streaming kernel ----------------
// bid % 5 == 0  -> GEMM role: tile bid/5 (32 rows): qM/fW projection, set flag.
// else          -> main role: 8 rows (warp-per-row), spin on tile flag
//                  (producer bid = 5*tile < consumer bid -> deadlock-free).
__global__ void __launch_bounds__(256, 4) unified_kernel(
    const float* __restrict__ feat, const float* __restrict__ knn_xyz,
    const float* __restrict__ knn_feat, const void* __restrict__ knn_mask,
    float* __restrict__ out_xyz, float* __restrict__ out_att, float* __restrict__ out_ml)
{
    __shared__ __align__(16) float As[TROWS * CDIM];   // 16 KB (GEMM role only)

    int bid  = blockIdx.x;
    int tid  = threadIdx.x;
    int lane = tid & 31;
    int warp = tid >> 5;

    if (bid % 5 == 0) {
        // ================= GEMM role =================
        int tile = bid / 5;
        int row0 = tile * TROWS;

        for (int i = tid; i < TROWS * 32; i += 256) {   // float4 units
            int r = i >> 5;
            float4 v = make_float4(0.f, 0.f, 0.f, 0.f);
            if (row0 + r < NROWS)
                v = reinterpret_cast<const float4*>(feat)[(size_t)(row0 + r) * 32 + (i & 31)];
            reinterpret_cast<float4*>(As)[i] = v;
        }
        __syncthreads();

        int cq = tid & 31;    // col quad cq*4..cq*4+3
        int rg = tid >> 5;    // 8 warps * 4 rows = 32 rows
        float accM[4][4], accW[4][4];
#pragma unroll
        for (int i = 0; i < 4; i++)
#pragma unroll
            for (int j = 0; j < 4; j++) { accM[i][j] = 0.f; accW[i][j] = 0.f; }

        const float* Ar = As + rg * 4 * CDIM;
#pragma unroll 4
        for (int k = 0; k < 128; k++) {
            float a[4];
#pragma unroll
            for (int i = 0; i < 4; i++) a[i] = Ar[i * CDIM + k];   // smem broadcast
            float4 bm = __ldg((const float4*)(g_M  + k * CDIM + cq * 4));
            float4 bw = __ldg((const float4*)(g_Ws + k * CDIM + cq * 4));
#pragma unroll
            for (int i = 0; i < 4; i++) {
                accM[i][0] += a[i] * bm.x; accM[i][1] += a[i] * bm.y;
                accM[i][2] += a[i] * bm.z; accM[i][3] += a[i] * bm.w;
                accW[i][0] += a[i] * bw.x; accW[i][1] += a[i] * bw.y;
                accW[i][2] += a[i] * bw.z; accW[i][3] += a[i] * bw.w;
            }
        }

#pragma unroll
        for (int i = 0; i < 4; i++) {
            int r = row0 + rg * 4 + i;
            if (r < NROWS) {
                reinterpret_cast<float4*>(g_qM + (size_t)r * CDIM)[cq] =
                    make_float4(accM[i][0], accM[i][1], accM[i][2], accM[i][3]);
                reinterpret_cast<float4*>(g_fW + (size_t)r * CDIM)[cq] =
                    make_float4(accW[i][0], accW[i][1], accW[i][2], accW[i][3]);
            }
        }
        __threadfence();
        __syncthreads();
        if (tid == 0) atomicExch(&g_tile_done[tile], 1);
        return;
    }

    // ================= main role (warp-per-row) =================
    int midx = bid - bid / 5 - 1;          // 0..6249
    int n    = midx * 8 + warp;            // this warp's row
    int tile = (midx * 8) / TROWS;         // all 8 rows in one tile

    const float4* kf4 = reinterpret_cast<const float4*>(knn_feat + (size_t)n * (KNB * CDIM));

    // prefetch kf into L2 while waiting for the projection tile
#pragma unroll
    for (int q = 0; q < 4; q++) {
        const char* p = (const char*)kf4 + (size_t)(lane + q * 32) * 128;
        asm volatile("prefetch.global.L2 [%0];" :: "l"(p));
    }

    if (lane == 0) {
        while (atomicAdd(&g_tile_done[tile], 0) == 0) __nanosleep(100);
    }
    __syncwarp();

    // COHERENT loads — g_qM/g_fW were written by another block this launch.
    float4 qv = ldcg4(reinterpret_cast<const float4*>(g_qM + (size_t)n * CDIM) + lane);
    float4 fv = ldcg4(reinterpret_cast<const float4*>(g_fW + (size_t)n * CDIM) + lane);

    float madj;
    if (g_mask_narrow)
        madj = ((const unsigned char*)knn_mask)[(size_t)n * KNB + lane] ? 0.f : -1e12f;
    else
        madj = ((const unsigned int*)knn_mask)[(size_t)n * KNB + lane] ? 0.f : -1e12f;
    float xj0 = __ldg(&knn_xyz[(size_t)n * 96 + lane * 3    ]);
    float xj1 = __ldg(&knn_xyz[(size_t)n * 96 + lane * 3 + 1]);
    float xj2 = __ldg(&knn_xyz[(size_t)n * 96 + lane * 3 + 2]);

    // dots: 8 batches of 4 neighbors; lane c-quad = lane*4..lane*4+3
    float myS = 0.f, myMl = 0.f;
#pragma unroll
    for (int b = 0; b < 8; b++) {
        float s[4], ml[4];
#pragma unroll
        for (int jj = 0; jj < 4; jj++) {
            float4 k4 = __ldg(kf4 + (b * 4 + jj) * 32 + lane);
            s [jj] = k4.x * qv.x + k4.y * qv.y + k4.z * qv.z + k4.w * qv.w;
            ml[jj] = k4.x * fv.x + k4.y * fv.y + k4.z * fv.z + k4.w * fv.w;
        }
#pragma unroll
        for (int o = 16; o; o >>= 1) {
#pragma unroll
            for (int jj = 0; jj < 4; jj++) {
                s [jj] += __shfl_xor_sync(0xffffffffu, s [jj], o);
                ml[jj] += __shfl_xor_sync(0xffffffffu, ml[jj], o);
            }
        }
#pragma unroll
        for (int jj = 0; jj < 4; jj++) {
            if (lane == b * 4 + jj) { myS = s[jj]; myMl = ml[jj]; }
        }
    }
    myS += madj;

    // rank (lax.top_k stable tie rule) — warp-local
    int rank = 0;
#pragma unroll
    for (int i = 0; i < KNB; i++) {
        float si = __shfl_sync(0xffffffffu, myS, i);
        rank += (si > myS) || (si == myS && i < lane);
    }
    if (rank < TOPK) {
        if (__ldcg(&g_colmask[lane]) == 0) atomicOr(&g_colmask[lane], 1);
    }
    g_scores[(size_t)n * KNB + lane] = myS;
    out_ml[(size_t)n * KNB + lane]   = myMl;

    // softmax — warp-local
    float m = myS;
#pragma unroll
    for (int o = 16; o; o >>= 1) m = fmaxf(m, __shfl_xor_sync(0xffffffffu, m, o));
    float e = __expf(myS - m);
    float ssum = e;
#pragma unroll
    for (int o = 16; o; o >>= 1) ssum += __shfl_xor_sync(0xffffffffu, ssum, o);
    float attn = e / ssum;

    // weighted sum: attn broadcast, kf re-read (L2 hits), lane -> channel quad
    float4 acc4 = make_float4(0.f, 0.f, 0.f, 0.f);
#pragma unroll
    for (int j = 0; j < KNB; j++) {
        float  a  = __shfl_sync(0xffffffffu, attn, j);
        float4 k4 = __ldg(kf4 + j * 32 + lane);
        acc4.x += a * k4.x; acc4.y += a * k4.y; acc4.z += a * k4.z; acc4.w += a * k4.w;
    }

    // xyz: lane j holds attn_j * xyz_j, butterfly-reduce 3 components
    float x0 = attn * xj0, x1 = attn * xj1, x2 = attn * xj2;
#pragma unroll
    for (int o = 16; o; o >>= 1) {
        x0 += __shfl_xor_sync(0xffffffffu, x0, o);
        x1 += __shfl_xor_sync(0xffffffffu, x1, o);
        x2 += __shfl_xor_sync(0xffffffffu, x2, o);
    }

    // outputs
    size_t ob = (size_t)n * 257;
    float4 f4 = __ldg(reinterpret_cast<const float4*>(feat + (size_t)n * CDIM) + lane);
    out_att[ob + lane * 4    ] = f4.x;
    out_att[ob + lane * 4 + 1] = f4.y;
    out_att[ob + lane * 4 + 2] = f4.z;
    out_att[ob + lane * 4 + 3] = f4.w;
    out_att[ob + 128 + lane * 4    ] = acc4.x;
    out_att[ob + 128 + lane * 4 + 1] = acc4.y;
    out_att[ob + 128 + lane * 4 + 2] = acc4.z;
    out_att[ob + 128 + lane * 4 + 3] = acc4.w;

    float p = fv.x * acc4.x + fv.y * acc4.y + fv.z * acc4.z + fv.w * acc4.w;
#pragma unroll
    for (int o = 16; o; o >>= 1) p += __shfl_xor_sync(0xffffffffu, p, o);
    if (lane == 0) {
        out_att[ob + 256] = p;                  // logit
        out_xyz[(size_t)n * 3    ] = x0;
        out_xyz[(size_t)n * 3 + 1] = x1;
        out_xyz[(size_t)n * 3 + 2] = x2;
    }
}

// ---------------- K2: check whether any column never made top-k ----------------
__global__ void check_kernel() {
    int t = threadIdx.x;
    int miss = (t < KNB && g_colmask[t] == 0) ? 1 : 0;
#pragma unroll
    for (int o = 16; o; o >>= 1) miss |= __shfl_xor_sync(0xffffffffu, miss, o);
    if (t == 0) g_needfix = miss;
}

// ---------------- K3: fixup (early-exits when colmask is all-covered) ----------------
__global__ void __launch_bounds__(128) fixup_kernel(
    const float* __restrict__ knn_feat, const float* __restrict__ knn_xyz,
    float* __restrict__ out_xyz, float* __restrict__ out_att)
{
    if (g_needfix == 0) return;   // common case

    __shared__ float attnS[KNB];
    __shared__ float redS[4];
    __shared__ int   colS[KNB];
    int tid = threadIdx.x, lane = tid & 31, warp = tid >> 5;
    if (tid < KNB) colS[tid] = g_colmask[tid];
    __syncthreads();

    for (int n = blockIdx.x; n < NROWS; n += gridDim.x) {
        if (tid < KNB) {
            float s  = g_scores[(size_t)n * KNB + tid];
            int inc  = colS[tid];
            float se = inc ? s : -3.0e38f;
            float m = se;
#pragma unroll
            for (int o = 16; o; o >>= 1) m = fmaxf(m, __shfl_xor_sync(0xffffffffu, m, o));
            float e = inc ? __expf(se - m) : 0.f;
            float ssum = e;
#pragma unroll
            for (int o = 16; o; o >>= 1) ssum += __shfl_xor_sync(0xffffffffu, ssum, o);
            attnS[tid] = e / ssum;
        }
        __syncthreads();

        float acc = 0.f;
#pragma unroll
        for (int j = 0; j < KNB; j++)
            acc += attnS[j] * knn_feat[(size_t)n * (KNB * CDIM) + j * CDIM + tid];

        size_t ob = (size_t)n * 257;
        out_att[ob + 128 + tid] = acc;

        float p = g_fW[(size_t)n * CDIM + tid] * acc;
#pragma unroll
        for (int o = 16; o; o >>= 1) p += __shfl_xor_sync(0xffffffffu, p, o);
        if (lane == 0) redS[warp] = p;
        __syncthreads();
        if (tid == 0) out_att[ob + 256] = redS[0] + redS[1] + redS[2] + redS[3];

        if (tid < 3) {
            float x = 0.f;
#pragma unroll
            for (int j = 0; j < KNB; j++)
                x += attnS[j] * knn_xyz[(size_t)n * (KNB * 3) + j * 3 + tid];
            out_xyz[(size_t)n * 3 + tid] = x;
        }
        __syncthreads();
    }
}

// ---------------- launch ----------------
extern "C" void kernel_launch(void* const* d_in, const int* in_sizes, int n_in,
                              void* d_out, int out_size) {
    const float* feat     = (const float*)d_in[0];          // [N,128]
    const float* knn_xyz  = (const float*)d_in[1];          // [N,32,3]
    const float* knn_feat = (const float*)d_in[2];          // [N,32,128]
    const void*  knn_mask = d_in[3];                        // [N,32] bool (width sniffed)
    const float* Wq       = (const float*)d_in[4];          // [128,128]
    const float* Wk       = (const float*)d_in[5];          // [128,128]
    const float* W        = (const float*)d_in[6];          // [128,128]

    float* out     = (float*)d_out;
    float* out_xyz = out;                                   // [N,3]
    float* out_att = out + (size_t)NROWS * 3;               // [N,257]
    float* out_ml  = out + (size_t)NROWS * 3 + (size_t)NROWS * 257;  // [N,32]

    prep_kernel<<<CDIM, CDIM>>>(Wq, Wk, W);
    sniff_kernel<<<512, 256>>>((const unsigned int*)knn_mask);

    unified_kernel<<<NBLK, 256>>>(feat, knn_xyz, knn_feat, knn_mask,
                                  out_xyz, out_att, out_ml);

    check_kernel<<<1, 32>>>();
    fixup_kernel<<<2048, CDIM>>>(knn_feat, knn_xyz, out_xyz, out_att);
}

// round 15
// speedup vs baseline: 2.3298x; 2.3298x over previous
#include <cuda_runtime.h>
#include <cuda_bf16.h>
#include <cstdint>

#define NROWS 50000
#define KNB   32
#define CDIM  128
#define TOPK  16
#define GR    128                         // rows per GEMM block
#define NGB   ((NROWS + GR - 1) / GR)     // 391
#define GEMM_SMEM (128*128*4 + 2*2*16*128*4)   // As 64KB + B 32KB = 98304

// ---------------- scratch (device globals; no allocation) ----------------
__device__ __align__(16) float g_M [CDIM * CDIM];     // Wq^T @ Wk
__device__ __align__(16) float g_Ws[CDIM * CDIM];     // triu(W) + triu(W)^T
__device__ __align__(16) float g_qM[(size_t)NROWS * CDIM];  // feat @ M
__device__ __align__(16) float g_fW[(size_t)NROWS * CDIM];  // feat @ Ws
__device__ __align__(16) float g_scores[(size_t)NROWS * KNB];
__device__ int g_colmask[KNB];
__device__ int g_mask_narrow;   // 1 -> mask elements are 1 byte; 0 -> 4 bytes

// ---------------- cp.async helpers ----------------
__device__ __forceinline__ void cp_async16(void* smem_dst, const void* gptr) {
    uint32_t s = (uint32_t)__cvta_generic_to_shared(smem_dst);
    asm volatile("cp.async.cg.shared.global [%0], [%1], 16;\n" :: "r"(s), "l"(gptr));
}
__device__ __forceinline__ void cp_async_commit() {
    asm volatile("cp.async.commit_group;\n" ::: "memory");
}
template <int N> __device__ __forceinline__ void cp_async_wait() {
    asm volatile("cp.async.wait_group %0;\n" :: "n"(N) : "memory");
}

// ---------------- K0: prep M, Ws, reset flags ----------------
__global__ void prep_kernel(const float* __restrict__ Wq,
                            const float* __restrict__ Wk,
                            const float* __restrict__ W) {
    int c = blockIdx.x;    // 0..127
    int e = threadIdx.x;   // 0..127
    float acc = 0.f;
#pragma unroll 8
    for (int d = 0; d < CDIM; d++)
        acc += Wq[d * CDIM + c] * Wk[d * CDIM + e];
    g_M[c * CDIM + e] = acc;

    float w = (c <= e) ? W[c * CDIM + e] : W[e * CDIM + c];
    g_Ws[c * CDIM + e] = (c == e) ? 2.f * w : w;

    if (c == 0 && e < KNB) g_colmask[e] = 0;
    if (c == 0 && e == KNB) g_mask_narrow = 0;
}

// ---------------- K0b: sniff knn_mask element width ----------------
__global__ void sniff_kernel(const unsigned int* __restrict__ w) {
    const int nwords = NROWS * KNB / 4;
    int bad = 0;
    for (int i = blockIdx.x * blockDim.x + threadIdx.x; i < nwords;
         i += gridDim.x * blockDim.x) {
        unsigned int v = w[i];
        if (v != 0u && v != 1u && v != 0x3F800000u) bad = 1;
    }
    if (bad) g_mask_narrow = 1;
}

// ---------------- K1: SGEMM v6 — 8x8 microtile, matrix-split, smem B ----------
// 512 threads: half 0 -> feat@M -> g_qM, half 1 -> feat@Ws -> g_fW.
// Per half: 256 threads = 16 row-groups x 16 col-groups, 8x8 microtile
// -> 1 B loaded per FMA -> FMA-bound (not L1/smem-bound like v4).
// A tile 128x128 in smem; B in double-buffered 16-k chunks via cp.async.
__global__ void __launch_bounds__(512, 1) gemm_kernel(const float* __restrict__ A) {
    extern __shared__ float sm[];
    float* As = sm;              // [128][128]
    float* Bs = sm + 128 * 128;  // M buf0 | M buf1 | W buf0 | W buf1 (2048 f each)

    int tid  = threadIdx.x;
    int half = tid >> 8;
    int t    = tid & 255;
    int rg   = t >> 4;           // rows rg*8 .. rg*8+7
    int cg   = t & 15;           // cols cg*8 .. cg*8+7
    int row0 = blockIdx.x * GR;

    // A tile: 4096 float4, 8 per thread (zero-pad past NROWS)
    for (int i = tid; i < 4096; i += 512) {
        int r = i >> 5;
        if (row0 + r < NROWS)
            cp_async16((float4*)As + i,
                       (const float4*)A + (size_t)(row0 + r) * 32 + (i & 31));
        else
            ((float4*)As)[i] = make_float4(0.f, 0.f, 0.f, 0.f);
    }
    // B chunk 0 into buf 0 (both matrices; 512 float4 each, 1 per thread)
    cp_async16((float4*)(Bs         ) + tid, (const float4*)g_M  + tid);
    cp_async16((float4*)(Bs + 4096  ) + tid, (const float4*)g_Ws + tid);
    cp_async_commit();                                   // G0: A + B0
    cp_async16((float4*)(Bs + 2048  ) + tid, (const float4*)g_M  + 512 + tid);
    cp_async16((float4*)(Bs + 6144  ) + tid, (const float4*)g_Ws + 512 + tid);
    cp_async_commit();                                   // G1: B1
    cp_async_wait<1>();                                  // G0 done
    __syncthreads();

    float acc[8][8];
#pragma unroll
    for (int i = 0; i < 8; i++)
#pragma unroll
        for (int j = 0; j < 8; j++) acc[i][j] = 0.f;

    const float* Bhalf = Bs + half * 4096;

    for (int c = 0; c < 8; c++) {
        const float* Bc = Bhalf + (c & 1) * 2048;
        const float* Ac = As + c * 16;
#pragma unroll
        for (int kk = 0; kk < 16; kk++) {
            float a[8];
#pragma unroll
            for (int i = 0; i < 8; i++)
                a[i] = Ac[(rg * 8 + i) * 128 + kk];
            float4 b0 = *(const float4*)(Bc + kk * 128 + cg * 8);
            float4 b1 = *(const float4*)(Bc + kk * 128 + cg * 8 + 4);
            float b[8] = {b0.x, b0.y, b0.z, b0.w, b1.x, b1.y, b1.z, b1.w};
#pragma unroll
            for (int i = 0; i < 8; i++)
#pragma unroll
                for (int j = 0; j < 8; j++) acc[i][j] += a[i] * b[j];
        }
        __syncthreads();                       // done reading buf c&1
        if (c + 2 < 8) {
            float* dst = Bs + (c & 1) * 2048;  // reuse freed buffer
            cp_async16((float4*)(dst       ) + tid,
                       (const float4*)g_M  + (c + 2) * 512 + tid);
            cp_async16((float4*)(dst + 4096) + tid,
                       (const float4*)g_Ws + (c + 2) * 512 + tid);
            cp_async_commit();
        }
        if (c + 1 < 8) {
            cp_async_wait<1>();                // chunk c+1 resident
            __syncthreads();
        }
    }

    float* __restrict__ Out = half ? g_fW : g_qM;
#pragma unroll
    for (int i = 0; i < 8; i++) {
        int r = row0 + rg * 8 + i;
        if (r < NROWS) {
            float4* p = (float4*)(Out + (size_t)r * 128 + cg * 8);
            p[0] = make_float4(acc[i][0], acc[i][1], acc[i][2], acc[i][3]);
            p[1] = make_float4(acc[i][4], acc[i][5], acc[i][6], acc[i][7]);
        }
    }
}

// ---------------- K2: warp-per-row streaming kernel (R12, measured 224us) ----
__global__ void __launch_bounds__(256, 5) main_kernel(
    const float* __restrict__ feat, const float* __restrict__ knn_xyz,
    const float* __restrict__ knn_feat, const void* __restrict__ knn_mask,
    float* __restrict__ out_xyz, float* __restrict__ out_att, float* __restrict__ out_ml)
{
    int tid  = threadIdx.x;
    int warp = tid >> 5;
    int lane = tid & 31;
    int n    = blockIdx.x * 8 + warp;

    const float4* kf4 = reinterpret_cast<const float4*>(knn_feat + (size_t)n * (KNB * CDIM));
    float4 qv = __ldg(reinterpret_cast<const float4*>(g_qM + (size_t)n * CDIM) + lane);
    float4 fv = __ldg(reinterpret_cast<const float4*>(g_fW + (size_t)n * CDIM) + lane);

    float madj;
    if (g_mask_narrow)
        madj = ((const unsigned char*)knn_mask)[(size_t)n * KNB + lane] ? 0.f : -1e12f;
    else
        madj = ((const unsigned int*)knn_mask)[(size_t)n * KNB + lane] ? 0.f : -1e12f;
    float xj0 = __ldg(&knn_xyz[(size_t)n * 96 + lane * 3    ]);
    float xj1 = __ldg(&knn_xyz[(size_t)n * 96 + lane * 3 + 1]);
    float xj2 = __ldg(&knn_xyz[(size_t)n * 96 + lane * 3 + 2]);

    // dots: 8 batches of 4 neighbors; lane c-quad = lane*4..lane*4+3
    float myS = 0.f, myMl = 0.f;
#pragma unroll
    for (int b = 0; b < 8; b++) {
        float s[4], ml[4];
#pragma unroll
        for (int jj = 0; jj < 4; jj++) {
            float4 k4 = __ldg(kf4 + (b * 4 + jj) * 32 + lane);
            s [jj] = k4.x * qv.x + k4.y * qv.y + k4.z * qv.z + k4.w * qv.w;
            ml[jj] = k4.x * fv.x + k4.y * fv.y + k4.z * fv.z + k4.w * fv.w;
        }
#pragma unroll
        for (int o = 16; o; o >>= 1) {
#pragma unroll
            for (int jj = 0; jj < 4; jj++) {
                s [jj] += __shfl_xor_sync(0xffffffffu, s [jj], o);
                ml[jj] += __shfl_xor_sync(0xffffffffu, ml[jj], o);
            }
        }
#pragma unroll
        for (int jj = 0; jj < 4; jj++) {
            if (lane == b * 4 + jj) { myS = s[jj]; myMl = ml[jj]; }
        }
    }
    myS += madj;

    // rank (lax.top_k stable tie rule) — warp-local
    int rank = 0;
#pragma unroll
    for (int i = 0; i < KNB; i++) {
        float si = __shfl_sync(0xffffffffu, myS, i);
        rank += (si > myS) || (si == myS && i < lane);
    }
    if (rank < TOPK) {
        if (__ldcg(&g_colmask[lane]) == 0) atomicOr(&g_colmask[lane], 1);
    }
    g_scores[(size_t)n * KNB + lane] = myS;
    out_ml[(size_t)n * KNB + lane]   = myMl;

    // softmax — warp-local
    float m = myS;
#pragma unroll
    for (int o = 16; o; o >>= 1) m = fmaxf(m, __shfl_xor_sync(0xffffffffu, m, o));
    float e = __expf(myS - m);
    float ssum = e;
#pragma unroll
    for (int o = 16; o; o >>= 1) ssum += __shfl_xor_sync(0xffffffffu, ssum, o);
    float attn = e / ssum;

    // weighted sum: attn broadcast, kf re-read (L2 hits), lane -> channel quad
    float4 acc4 = make_float4(0.f, 0.f, 0.f, 0.f);
#pragma unroll
    for (int j = 0; j < KNB; j++) {
        float  a  = __shfl_sync(0xffffffffu, attn, j);
        float4 k4 = __ldg(kf4 + j * 32 + lane);
        acc4.x += a * k4.x; acc4.y += a * k4.y; acc4.z += a * k4.z; acc4.w += a * k4.w;
    }

    // xyz: lane j holds attn_j * xyz_j, butterfly-reduce 3 components
    float x0 = attn * xj0, x1 = attn * xj1, x2 = attn * xj2;
#pragma unroll
    for (int o = 16; o; o >>= 1) {
        x0 += __shfl_xor_sync(0xffffffffu, x0, o);
        x1 += __shfl_xor_sync(0xffffffffu, x1, o);
        x2 += __shfl_xor_sync(0xffffffffu, x2, o);
    }

    // outputs
    size_t ob = (size_t)n * 257;
    float4 f4 = __ldg(reinterpret_cast<const float4*>(feat + (size_t)n * CDIM) + lane);
    out_att[ob + lane * 4    ] = f4.x;
    out_att[ob + lane * 4 + 1] = f4.y;
    out_att[ob + lane * 4 + 2] = f4.z;
    out_att[ob + lane * 4 + 3] = f4.w;
    out_att[ob + 128 + lane * 4    ] = acc4.x;
    out_att[ob + 128 + lane * 4 + 1] = acc4.y;
    out_att[ob + 128 + lane * 4 + 2] = acc4.z;
    out_att[ob + 128 + lane * 4 + 3] = acc4.w;

    float p = fv.x * acc4.x + fv.y * acc4.y + fv.z * acc4.z + fv.w * acc4.w;
#pragma unroll
    for (int o = 16; o; o >>= 1) p += __shfl_xor_sync(0xffffffffu, p, o);
    if (lane == 0) {
        out_att[ob + 256] = p;                  // logit
        out_xyz[(size_t)n * 3    ] = x0;
        out_xyz[(size_t)n * 3 + 1] = x1;
        out_xyz[(size_t)n * 3 + 2] = x2;
    }
}

// ---------------- K3: fixup (computes needfix itself; rare path) ----------------
__global__ void __launch_bounds__(128) fixup_kernel(
    const float* __restrict__ knn_feat, const float* __restrict__ knn_xyz,
    float* __restrict__ out_xyz, float* __restrict__ out_att)
{
    __shared__ float attnS[KNB];
    __shared__ float redS[4];
    __shared__ int   colS[KNB];
    __shared__ int   needS;
    int tid = threadIdx.x, lane = tid & 31, warp = tid >> 5;
    if (tid < KNB) colS[tid] = g_colmask[tid];
    __syncthreads();
    if (tid == 0) {
        int nf = 0;
        for (int j = 0; j < KNB; j++) nf |= (colS[j] == 0);
        needS = nf;
    }
    __syncthreads();
    if (needS == 0) return;   // common case: every column covered

    for (int n = blockIdx.x; n < NROWS; n += gridDim.x) {
        if (tid < KNB) {
            float s  = g_scores[(size_t)n * KNB + tid];
            int inc  = colS[tid];
            float se = inc ? s : -3.0e38f;
            float m = se;
#pragma unroll
            for (int o = 16; o; o >>= 1) m = fmaxf(m, __shfl_xor_sync(0xffffffffu, m, o));
            float e = inc ? __expf(se - m) : 0.f;
            float ssum = e;
#pragma unroll
            for (int o = 16; o; o >>= 1) ssum += __shfl_xor_sync(0xffffffffu, ssum, o);
            attnS[tid] = e / ssum;
        }
        __syncthreads();

        float acc = 0.f;
#pragma unroll
        for (int j = 0; j < KNB; j++)
            acc += attnS[j] * knn_feat[(size_t)n * (KNB * CDIM) + j * CDIM + tid];

        size_t ob = (size_t)n * 257;
        out_att[ob + 128 + tid] = acc;

        float p = g_fW[(size_t)n * CDIM + tid] * acc;
#pragma unroll
        for (int o = 16; o; o >>= 1) p += __shfl_xor_sync(0xffffffffu, p, o);
        if (lane == 0) redS[warp] = p;
        __syncthreads();
        if (tid == 0) out_att[ob + 256] = redS[0] + redS[1] + redS[2] + redS[3];

        if (tid < 3) {
            float x = 0.f;
#pragma unroll
            for (int j = 0; j < KNB; j++)
                x += attnS[j] * knn_xyz[(size_t)n * (KNB * 3) + j * 3 + tid];
            out_xyz[(size_t)n * 3 + tid] = x;
        }
        __syncthreads();
    }
}

// ---------------- launch ----------------
extern "C" void kernel_launch(void* const* d_in, const int* in_sizes, int n_in,
                              void* d_out, int out_size) {
    const float* feat     = (const float*)d_in[0];          // [N,128]
    const float* knn_xyz  = (const float*)d_in[1];          // [N,32,3]
    const float* knn_feat = (const float*)d_in[2];          // [N,32,128]
    const void*  knn_mask = d_in[3];                        // [N,32] bool (width sniffed)
    const float* Wq       = (const float*)d_in[4];          // [128,128]
    const float* Wk       = (const float*)d_in[5];          // [128,128]
    const float* W        = (const float*)d_in[6];          // [128,128]

    float* out     = (float*)d_out;
    float* out_xyz = out;                                   // [N,3]
    float* out_att = out + (size_t)NROWS * 3;               // [N,257]
    float* out_ml  = out + (size_t)NROWS * 3 + (size_t)NROWS * 257;  // [N,32]

    prep_kernel<<<CDIM, CDIM>>>(Wq, Wk, W);
    sniff_kernel<<<512, 256>>>((const unsigned int*)knn_mask);

    cudaFuncSetAttribute(gemm_kernel, cudaFuncAttributeMaxDynamicSharedMemorySize,
                         GEMM_SMEM);
    gemm_kernel<<<NGB, 512, GEMM_SMEM>>>(feat);

    main_kernel<<<NROWS / 8, 256>>>(feat, knn_xyz, knn_feat, knn_mask,
                                    out_xyz, out_att, out_ml);

    fixup_kernel<<<2048, CDIM>>>(knn_feat, knn_xyz, out_xyz, out_att);
}

// round 16
// speedup vs baseline: 2.8873x; 1.2393x over previous
#include <cuda_runtime.h>
#include <cuda_bf16.h>
#include <cstdint>

#define NROWS 50000
#define KNB   32
#define CDIM  128
#define TOPK  16
#define GR    128                         // rows per GEMM block
#define NGB   ((NROWS + GR - 1) / GR)     // 391
#define GEMM_SMEM (128*128*4 + 2*2*16*128*4)   // As 64KB + B 32KB = 98304

// ---------------- scratch (device globals; no allocation) ----------------
__device__ __align__(16) float g_M [CDIM * CDIM];     // Wq^T @ Wk
__device__ __align__(16) float g_Ws[CDIM * CDIM];     // triu(W) + triu(W)^T
__device__ __align__(16) float g_qM[(size_t)NROWS * CDIM];  // feat @ M
__device__ __align__(16) float g_fW[(size_t)NROWS * CDIM];  // feat @ Ws
__device__ __align__(16) float g_scores[(size_t)NROWS * KNB];
__device__ int g_colmask[KNB];
__device__ int g_mask_narrow;   // 1 -> mask elements are 1 byte; 0 -> 4 bytes

// ---------------- cp.async helpers ----------------
__device__ __forceinline__ void cp_async16(void* smem_dst, const void* gptr) {
    uint32_t s = (uint32_t)__cvta_generic_to_shared(smem_dst);
    asm volatile("cp.async.cg.shared.global [%0], [%1], 16;\n" :: "r"(s), "l"(gptr));
}
__device__ __forceinline__ void cp_async_commit() {
    asm volatile("cp.async.commit_group;\n" ::: "memory");
}
template <int N> __device__ __forceinline__ void cp_async_wait() {
    asm volatile("cp.async.wait_group %0;\n" :: "n"(N) : "memory");
}

// ---------------- K0: prep M, Ws, reset flags ----------------
__global__ void prep_kernel(const float* __restrict__ Wq,
                            const float* __restrict__ Wk,
                            const float* __restrict__ W) {
    int c = blockIdx.x;    // 0..127
    int e = threadIdx.x;   // 0..127
    float acc = 0.f;
#pragma unroll 8
    for (int d = 0; d < CDIM; d++)
        acc += Wq[d * CDIM + c] * Wk[d * CDIM + e];
    g_M[c * CDIM + e] = acc;

    float w = (c <= e) ? W[c * CDIM + e] : W[e * CDIM + c];
    g_Ws[c * CDIM + e] = (c == e) ? 2.f * w : w;

    if (c == 0 && e < KNB) g_colmask[e] = 0;
    if (c == 0 && e == KNB) g_mask_narrow = 0;
}

// ---------------- K0b: sniff knn_mask element width ----------------
__global__ void sniff_kernel(const unsigned int* __restrict__ w) {
    const int nwords = NROWS * KNB / 4;
    int bad = 0;
    for (int i = blockIdx.x * blockDim.x + threadIdx.x; i < nwords;
         i += gridDim.x * blockDim.x) {
        unsigned int v = w[i];
        if (v != 0u && v != 1u && v != 0x3F800000u) bad = 1;
    }
    if (bad) g_mask_narrow = 1;
}

// ---------------- K1: SGEMM v6 (unchanged from R15; ~near FFMA floor) --------
__global__ void __launch_bounds__(512, 1) gemm_kernel(const float* __restrict__ A) {
    extern __shared__ float sm[];
    float* As = sm;              // [128][128]
    float* Bs = sm + 128 * 128;  // M buf0 | M buf1 | W buf0 | W buf1 (2048 f each)

    int tid  = threadIdx.x;
    int half = tid >> 8;
    int t    = tid & 255;
    int rg   = t >> 4;           // rows rg*8 .. rg*8+7
    int cg   = t & 15;           // cols cg*8 .. cg*8+7
    int row0 = blockIdx.x * GR;

    for (int i = tid; i < 4096; i += 512) {
        int r = i >> 5;
        if (row0 + r < NROWS)
            cp_async16((float4*)As + i,
                       (const float4*)A + (size_t)(row0 + r) * 32 + (i & 31));
        else
            ((float4*)As)[i] = make_float4(0.f, 0.f, 0.f, 0.f);
    }
    cp_async16((float4*)(Bs         ) + tid, (const float4*)g_M  + tid);
    cp_async16((float4*)(Bs + 4096  ) + tid, (const float4*)g_Ws + tid);
    cp_async_commit();                                   // G0: A + B0
    cp_async16((float4*)(Bs + 2048  ) + tid, (const float4*)g_M  + 512 + tid);
    cp_async16((float4*)(Bs + 6144  ) + tid, (const float4*)g_Ws + 512 + tid);
    cp_async_commit();                                   // G1: B1
    cp_async_wait<1>();                                  // G0 done
    __syncthreads();

    float acc[8][8];
#pragma unroll
    for (int i = 0; i < 8; i++)
#pragma unroll
        for (int j = 0; j < 8; j++) acc[i][j] = 0.f;

    const float* Bhalf = Bs + half * 4096;

    for (int c = 0; c < 8; c++) {
        const float* Bc = Bhalf + (c & 1) * 2048;
        const float* Ac = As + c * 16;
#pragma unroll
        for (int kk = 0; kk < 16; kk++) {
            float a[8];
#pragma unroll
            for (int i = 0; i < 8; i++)
                a[i] = Ac[(rg * 8 + i) * 128 + kk];
            float4 b0 = *(const float4*)(Bc + kk * 128 + cg * 8);
            float4 b1 = *(const float4*)(Bc + kk * 128 + cg * 8 + 4);
            float b[8] = {b0.x, b0.y, b0.z, b0.w, b1.x, b1.y, b1.z, b1.w};
#pragma unroll
            for (int i = 0; i < 8; i++)
#pragma unroll
                for (int j = 0; j < 8; j++) acc[i][j] += a[i] * b[j];
        }
        __syncthreads();                       // done reading buf c&1
        if (c + 2 < 8) {
            float* dst = Bs + (c & 1) * 2048;  // reuse freed buffer
            cp_async16((float4*)(dst       ) + tid,
                       (const float4*)g_M  + (c + 2) * 512 + tid);
            cp_async16((float4*)(dst + 4096) + tid,
                       (const float4*)g_Ws + (c + 2) * 512 + tid);
            cp_async_commit();
        }
        if (c + 1 < 8) {
            cp_async_wait<1>();                // chunk c+1 resident
            __syncthreads();
        }
    }

    float* __restrict__ Out = half ? g_fW : g_qM;
#pragma unroll
    for (int i = 0; i < 8; i++) {
        int r = row0 + rg * 8 + i;
        if (r < NROWS) {
            float4* p = (float4*)(Out + (size_t)r * 128 + cg * 8);
            p[0] = make_float4(acc[i][0], acc[i][1], acc[i][2], acc[i][3]);
            p[1] = make_float4(acc[i][4], acc[i][5], acc[i][6], acc[i][7]);
        }
    }
}

// ---------------- K2: warp-per-row, SINGLE-PASS online softmax ----------------
// kf is touched exactly once: per batch of 4 neighbors, dot-reduce s & ml,
// then (kf regs still live) online-update acc4/sum/m. Kills the phase-3
// re-read that was missing L2 (~400MB extra DRAM in R15's profile).
__global__ void __launch_bounds__(256, 5) main_kernel(
    const float* __restrict__ feat, const float* __restrict__ knn_xyz,
    const float* __restrict__ knn_feat, const void* __restrict__ knn_mask,
    float* __restrict__ out_xyz, float* __restrict__ out_att, float* __restrict__ out_ml)
{
    int tid  = threadIdx.x;
    int warp = tid >> 5;
    int lane = tid & 31;
    int n    = blockIdx.x * 8 + warp;

    const float4* kf4 = reinterpret_cast<const float4*>(knn_feat + (size_t)n * (KNB * CDIM));
    float4 qv = __ldg(reinterpret_cast<const float4*>(g_qM + (size_t)n * CDIM) + lane);
    float4 fv = __ldg(reinterpret_cast<const float4*>(g_fW + (size_t)n * CDIM) + lane);

    // lane j's mask adjust + xyz triplet
    float madj;
    if (g_mask_narrow)
        madj = ((const unsigned char*)knn_mask)[(size_t)n * KNB + lane] ? 0.f : -1e12f;
    else
        madj = ((const unsigned int*)knn_mask)[(size_t)n * KNB + lane] ? 0.f : -1e12f;
    float xj0 = __ldg(&knn_xyz[(size_t)n * 96 + lane * 3    ]);
    float xj1 = __ldg(&knn_xyz[(size_t)n * 96 + lane * 3 + 1]);
    float xj2 = __ldg(&knn_xyz[(size_t)n * 96 + lane * 3 + 2]);

    float myS = 0.f, myMl = 0.f;
    float m_run = -3.0e38f, sum = 0.f;
    float4 acc4 = make_float4(0.f, 0.f, 0.f, 0.f);

#pragma unroll
    for (int b = 0; b < 8; b++) {
        float4 kf[4];
        float s[4], ml[4];
#pragma unroll
        for (int jj = 0; jj < 4; jj++) {
            kf[jj] = __ldg(kf4 + (b * 4 + jj) * 32 + lane);
            s [jj] = kf[jj].x * qv.x + kf[jj].y * qv.y + kf[jj].z * qv.z + kf[jj].w * qv.w;
            ml[jj] = kf[jj].x * fv.x + kf[jj].y * fv.y + kf[jj].z * fv.z + kf[jj].w * fv.w;
        }
#pragma unroll
        for (int o = 16; o; o >>= 1) {
#pragma unroll
            for (int jj = 0; jj < 4; jj++) {
                s [jj] += __shfl_xor_sync(0xffffffffu, s [jj], o);
                ml[jj] += __shfl_xor_sync(0xffffffffu, ml[jj], o);
            }
        }
        // online update, kf regs still live
#pragma unroll
        for (int jj = 0; jj < 4; jj++) {
            int j = b * 4 + jj;
            float sj = s[jj] + __shfl_sync(0xffffffffu, madj, j);   // warp-uniform
            if (lane == j) { myS = sj; myMl = ml[jj]; }
            float m_new = fmaxf(m_run, sj);
            float sc = __expf(m_run - m_new);
            float e  = __expf(sj - m_new);
            acc4.x = acc4.x * sc + e * kf[jj].x;
            acc4.y = acc4.y * sc + e * kf[jj].y;
            acc4.z = acc4.z * sc + e * kf[jj].z;
            acc4.w = acc4.w * sc + e * kf[jj].w;
            sum    = sum    * sc + e;
            m_run  = m_new;
        }
    }

    // normalize
    float inv = 1.f / sum;
    acc4.x *= inv; acc4.y *= inv; acc4.z *= inv; acc4.w *= inv;
    float attn = __expf(myS - m_run) * inv;        // lane's own neighbor weight

    // rank (lax.top_k stable tie rule) — warp-local on adjusted scores
    int rank = 0;
#pragma unroll
    for (int i = 0; i < KNB; i++) {
        float si = __shfl_sync(0xffffffffu, myS, i);
        rank += (si > myS) || (si == myS && i < lane);
    }
    if (rank < TOPK) {
        if (__ldcg(&g_colmask[lane]) == 0) atomicOr(&g_colmask[lane], 1);
    }
    g_scores[(size_t)n * KNB + lane] = myS;
    out_ml[(size_t)n * KNB + lane]   = myMl;

    // xyz: lane j holds attn_j * xyz_j, butterfly-reduce 3 components
    float x0 = attn * xj0, x1 = attn * xj1, x2 = attn * xj2;
#pragma unroll
    for (int o = 16; o; o >>= 1) {
        x0 += __shfl_xor_sync(0xffffffffu, x0, o);
        x1 += __shfl_xor_sync(0xffffffffu, x1, o);
        x2 += __shfl_xor_sync(0xffffffffu, x2, o);
    }

    // outputs
    size_t ob = (size_t)n * 257;
    float4 f4 = __ldg(reinterpret_cast<const float4*>(feat + (size_t)n * CDIM) + lane);
    out_att[ob + lane * 4    ] = f4.x;
    out_att[ob + lane * 4 + 1] = f4.y;
    out_att[ob + lane * 4 + 2] = f4.z;
    out_att[ob + lane * 4 + 3] = f4.w;
    out_att[ob + 128 + lane * 4    ] = acc4.x;
    out_att[ob + 128 + lane * 4 + 1] = acc4.y;
    out_att[ob + 128 + lane * 4 + 2] = acc4.z;
    out_att[ob + 128 + lane * 4 + 3] = acc4.w;

    float p = fv.x * acc4.x + fv.y * acc4.y + fv.z * acc4.z + fv.w * acc4.w;
#pragma unroll
    for (int o = 16; o; o >>= 1) p += __shfl_xor_sync(0xffffffffu, p, o);
    if (lane == 0) {
        out_att[ob + 256] = p;                  // logit
        out_xyz[(size_t)n * 3    ] = x0;
        out_xyz[(size_t)n * 3 + 1] = x1;
        out_xyz[(size_t)n * 3 + 2] = x2;
    }
}

// ---------------- K3: fixup (computes needfix itself; rare path) ----------------
__global__ void __launch_bounds__(128) fixup_kernel(
    const float* __restrict__ knn_feat, const float* __restrict__ knn_xyz,
    float* __restrict__ out_xyz, float* __restrict__ out_att)
{
    __shared__ float attnS[KNB];
    __shared__ float redS[4];
    __shared__ int   colS[KNB];
    __shared__ int   needS;
    int tid = threadIdx.x, lane = tid & 31, warp = tid >> 5;
    if (tid < KNB) colS[tid] = g_colmask[tid];
    __syncthreads();
    if (tid == 0) {
        int nf = 0;
        for (int j = 0; j < KNB; j++) nf |= (colS[j] == 0);
        needS = nf;
    }
    __syncthreads();
    if (needS == 0) return;   // common case: every column covered

    for (int n = blockIdx.x; n < NROWS; n += gridDim.x) {
        if (tid < KNB) {
            float s  = g_scores[(size_t)n * KNB + tid];
            int inc  = colS[tid];
            float se = inc ? s : -3.0e38f;
            float m = se;
#pragma unroll
            for (int o = 16; o; o >>= 1) m = fmaxf(m, __shfl_xor_sync(0xffffffffu, m, o));
            float e = inc ? __expf(se - m) : 0.f;
            float ssum = e;
#pragma unroll
            for (int o = 16; o; o >>= 1) ssum += __shfl_xor_sync(0xffffffffu, ssum, o);
            attnS[tid] = e / ssum;
        }
        __syncthreads();

        float acc = 0.f;
#pragma unroll
        for (int j = 0; j < KNB; j++)
            acc += attnS[j] * knn_feat[(size_t)n * (KNB * CDIM) + j * CDIM + tid];

        size_t ob = (size_t)n * 257;
        out_att[ob + 128 + tid] = acc;

        float p = g_fW[(size_t)n * CDIM + tid] * acc;
#pragma unroll
        for (int o = 16; o; o >>= 1) p += __shfl_xor_sync(0xffffffffu, p, o);
        if (lane == 0) redS[warp] = p;
        __syncthreads();
        if (tid == 0) out_att[ob + 256] = redS[0] + redS[1] + redS[2] + redS[3];

        if (tid < 3) {
            float x = 0.f;
#pragma unroll
            for (int j = 0; j < KNB; j++)
                x += attnS[j] * knn_xyz[(size_t)n * (KNB * 3) + j * 3 + tid];
            out_xyz[(size_t)n * 3 + tid] = x;
        }
        __syncthreads();
    }
}

// ---------------- launch ----------------
extern "C" void kernel_launch(void* const* d_in, const int* in_sizes, int n_in,
                              void* d_out, int out_size) {
    const float* feat     = (const float*)d_in[0];          // [N,128]
    const float* knn_xyz  = (const float*)d_in[1];          // [N,32,3]
    const float* knn_feat = (const float*)d_in[2];          // [N,32,128]
    const void*  knn_mask = d_in[3];                        // [N,32] bool (width sniffed)
    const float* Wq       = (const float*)d_in[4];          // [128,128]
    const float* Wk       = (const float*)d_in[5];          // [128,128]
    const float* W        = (const float*)d_in[6];          // [128,128]

    float* out     = (float*)d_out;
    float* out_xyz = out;                                   // [N,3]
    float* out_att = out + (size_t)NROWS * 3;               // [N,257]
    float* out_ml  = out + (size_t)NROWS * 3 + (size_t)NROWS * 257;  // [N,32]

    prep_kernel<<<CDIM, CDIM>>>(Wq, Wk, W);
    sniff_kernel<<<512, 256>>>((const unsigned int*)knn_mask);

    cudaFuncSetAttribute(gemm_kernel, cudaFuncAttributeMaxDynamicSharedMemorySize,
                         GEMM_SMEM);
    gemm_kernel<<<NGB, 512, GEMM_SMEM>>>(feat);

    main_kernel<<<NROWS / 8, 256>>>(feat, knn_xyz, knn_feat, knn_mask,
                                    out_xyz, out_att, out_ml);

    fixup_kernel<<<2048, CDIM>>>(knn_feat, knn_xyz, out_xyz, out_att);
}